// round 3
// baseline (speedup 1.0000x reference)
#include <cuda_runtime.h>

// BinsChamferLoss: n=16, d=128, h=192, w=256.  Single fused kernel.
// out[b] = (loss1[b] + loss2[b]) / sum(valid_mask)   (count over ALL batches)
//   g = valid ? max(t, bins[b][0]) : bins[b][0]
//   loss1[b] = sum_pixels min_bins |g - bin|   (binary search, bins sorted)
//   loss2[b] = sum_bins  min_pixels |g - bin|  (segment min/max + prefix/suffix scans)
//
// Graph-replay safe without an init kernel: per-block partial slots are plain-
// stored (fully overwritten each launch); tickets are reset by their last user.

#define NB   16
#define DB   128
#define HW   49152            // 192*256
#define BPB  24               // blocks per batch
#define PPB  (HW / BPB)       // 2048 pixels per block
#define TH   256
#define NSEG (DB + 1)         // segment s in [1,128]; slot 0 unused
#define INF_BITS 0x7F800000

// Per-block partials (no init required; overwritten every replay).
__device__ float        g_pl1 [NB * BPB];
__device__ unsigned int g_pcnt[NB * BPB];
__device__ int          g_pmax[NB * BPB * NSEG];   // float bits; -1 = empty
__device__ int          g_pmin[NB * BPB * NSEG];   // INF_BITS = empty
// Per-batch results + tickets (tickets: 0 -> ... -> reset to 0 by last user).
__device__ float        g_bsum[NB];
__device__ unsigned int g_bcnt[NB];
__device__ unsigned int g_tick_b[NB];
__device__ unsigned int g_tick_g;

__global__ __launch_bounds__(TH) void bcl_fused(const float* __restrict__ bins,
                                                const float* __restrict__ tdm,
                                                const int*   __restrict__ mask,
                                                float*       __restrict__ out) {
    const int batch = blockIdx.x / BPB;
    const int blk   = blockIdx.x % BPB;
    const int bid   = blockIdx.x;
    const int tid   = threadIdx.x;

    __shared__ float sb[NSEG];          // bins + inf pad
    __shared__ int   spmax[NSEG];
    __shared__ int   spmin[NSEG];
    __shared__ int   sflag;             // any invalid pixel seen
    __shared__ float        wl[TH / 32];
    __shared__ unsigned int wc[TH / 32];
    __shared__ unsigned int s_tick;

    if (tid < DB)   sb[tid] = bins[batch * DB + tid];
    if (tid == DB)  sb[DB]  = __int_as_float(INF_BITS);
    for (int i = tid; i < NSEG; i += TH) { spmax[i] = -1; spmin[i] = INF_BITS; }
    if (tid == 0) sflag = 0;
    __syncthreads();

    const float b0 = sb[0];
    float loss1 = 0.0f;
    unsigned int cnt = 0;
    bool sawInvalid = false;

    const int base = batch * HW + blk * PPB;
    const float4* t4 = (const float4*)(tdm + base);
    const int4*   m4 = (const int4*)(mask + base);

    #pragma unroll
    for (int it = 0; it < PPB / (4 * TH); it++) {       // 2 iterations, 8 px/thread
        const int i = it * TH + tid;
        const float4 tv = t4[i];
        const int4   mv = m4[i];
        const float gv[4] = {tv.x, tv.y, tv.z, tv.w};
        const int   mk[4] = {mv.x, mv.y, mv.z, mv.w};
        #pragma unroll
        for (int k = 0; k < 4; k++) {
            const bool v = (mk[k] != 0);
            const float g = v ? fmaxf(gv[k], b0) : b0;
            // upper_bound: first s with sb[s] > g; s in [1,128] since sb[0] <= g.
            int lo = 0, hi = DB;
            #pragma unroll
            for (int bs = 0; bs < 8; bs++) {
                const int mid = (lo + hi) >> 1;
                if (sb[mid] <= g) lo = mid + 1; else hi = mid;
            }
            const int s = lo;
            loss1 += fminf(g - sb[s - 1], sb[s] - g);    // 0 for invalid (g==b0)
            if (v) {
                cnt++;
                const int gi = __float_as_int(g);        // g>0: int order == float order
                atomicMax(&spmax[s], gi);
                atomicMin(&spmin[s], gi);
            } else {
                sawInvalid = true;
            }
        }
    }
    if (sawInvalid) sflag = 1;                           // benign race
    __syncthreads();

    if (tid == 0 && sflag) {                             // single b0 update for all invalids
        int lo = 0, hi = DB;
        for (int bs = 0; bs < 8; bs++) {
            const int mid = (lo + hi) >> 1;
            if (sb[mid] <= b0) lo = mid + 1; else hi = mid;
        }
        const int bi = __float_as_int(b0);
        atomicMax(&spmax[lo], bi);
        atomicMin(&spmin[lo], bi);
    }

    // block reduce loss1 & count
    #pragma unroll
    for (int off = 16; off; off >>= 1) {
        loss1 += __shfl_down_sync(0xFFFFFFFFu, loss1, off);
        cnt   += __shfl_down_sync(0xFFFFFFFFu, cnt,   off);
    }
    if ((tid & 31) == 0) { wl[tid >> 5] = loss1; wc[tid >> 5] = cnt; }
    __syncthreads();

    // publish partials
    if (tid == 0) {
        float L = 0.0f; unsigned int C = 0;
        #pragma unroll
        for (int w = 0; w < TH / 32; w++) { L += wl[w]; C += wc[w]; }
        g_pl1[bid] = L; g_pcnt[bid] = C;
    }
    for (int i = tid; i < NSEG; i += TH) {
        g_pmax[bid * NSEG + i] = spmax[i];
        g_pmin[bid * NSEG + i] = spmin[i];
    }
    __threadfence();
    if (tid == 0) s_tick = atomicAdd(&g_tick_b[batch], 1u);
    __syncthreads();
    if (s_tick != BPB - 1) return;

    // ---------------- batch finalizer (one block per batch) ----------------
    __threadfence();
    if (tid == 0) g_tick_b[batch] = 0;                   // reset for next replay

    __shared__ float pref[NSEG], suf[NSEG];
    if (tid < NSEG) {
        int mx = -1, mn = INF_BITS;
        const int mbase = (batch * BPB) * NSEG + tid;
        #pragma unroll 4
        for (int b = 0; b < BPB; b++) {
            mx = max(mx, g_pmax[mbase + b * NSEG]);
            mn = min(mn, g_pmin[mbase + b * NSEG]);
        }
        pref[tid] = (mx == -1)       ? -1e30f : __int_as_float(mx);
        suf [tid] = (mn == INF_BITS) ?  1e30f : __int_as_float(mn);
    }
    float L = 0.0f; unsigned int C = 0;
    if (tid < 32) {
        if (tid < BPB) { L = g_pl1[batch * BPB + tid]; C = g_pcnt[batch * BPB + tid]; }
        #pragma unroll
        for (int off = 16; off; off >>= 1) {
            L += __shfl_down_sync(0xFFFFFFFFu, L, off);
            C += __shfl_down_sync(0xFFFFFFFFu, C, off);
        }
    }
    __syncthreads();

    if (tid == 0) {                                      // in-place 129-entry scans
        float r = -1e30f;
        for (int s = 0; s < NSEG; s++) { r = fmaxf(r, pref[s]); pref[s] = r; }
        float r2 = 1e30f;
        for (int s = NSEG - 1; s >= 0; s--) { r2 = fminf(r2, suf[s]); suf[s] = r2; }
    }
    __syncthreads();

    float v = 0.0f;
    if (tid < DB) {
        const float bj = sb[tid];
        v = fminf(bj - pref[tid], suf[tid + 1] - bj);    // exact per-bin min dist
    }
    #pragma unroll
    for (int off = 16; off; off >>= 1) v += __shfl_down_sync(0xFFFFFFFFu, v, off);
    if ((tid & 31) == 0) wl[tid >> 5] = v;
    __syncthreads();

    if (tid == 0) {
        const float loss2 = wl[0] + wl[1] + wl[2] + wl[3];
        g_bsum[batch] = L + loss2;
        g_bcnt[batch] = C;
        __threadfence();
        const unsigned int t2 = atomicAdd(&g_tick_g, 1u);
        if (t2 == NB - 1) {                              // global finalizer
            g_tick_g = 0;
            __threadfence();
            unsigned int tot = 0;
            #pragma unroll
            for (int b = 0; b < NB; b++) tot += g_bcnt[b];
            const float inv = 1.0f / (float)tot;
            #pragma unroll
            for (int b = 0; b < NB; b++) out[b] = g_bsum[b] * inv;
        }
    }
}

extern "C" void kernel_launch(void* const* d_in, const int* in_sizes, int n_in,
                              void* d_out, int out_size) {
    const float* bins = (const float*)d_in[0];
    const float* tdm  = (const float*)d_in[1];
    const int*   msk  = (const int*)d_in[2];
    float*       out  = (float*)d_out;

    bcl_fused<<<NB * BPB, TH>>>(bins, tdm, msk, out);
}

// round 4
// speedup vs baseline: 1.0276x; 1.0276x over previous
#include <cuda_runtime.h>

// BinsChamferLoss: n=16, d=128, h=192, w=256.  Single fused kernel.
// out[b] = (loss1[b] + loss2[b]) / sum(valid_mask)   (count over ALL batches)
//   g = valid ? max(t, bins[b][0]) : bins[b][0]
//   loss1[b] = sum_pixels min_bins |g - bin|   (Eytzinger-layout binary search)
//   loss2[b] = sum_bins  min_pixels |g - bin|  (segment min/max + prefix/suffix scans)
//
// Perf notes vs R3: (1) BFS/Eytzinger tree removes the structural 8-way bank
// conflicts of linear-layout binary search; (2) shared atomics are guarded by
// an LDS read (monotonic, race-safe) so ATOMS throughput cost disappears.

#define NB   16
#define DB   128
#define HW   49152            // 192*256
#define BPB  24               // blocks per batch
#define PPB  (HW / BPB)       // 2048 pixels per block
#define TH   256
#define NSEG (DB + 1)         // segment s in [1,128]; slot 0 unused
#define INF_BITS 0x7F800000

// Per-block partials (no init required; overwritten every replay).
__device__ float        g_pl1 [NB * BPB];
__device__ unsigned int g_pcnt[NB * BPB];
__device__ int          g_pmax[NB * BPB * NSEG];   // float bits; -1 = empty
__device__ int          g_pmin[NB * BPB * NSEG];   // INF_BITS = empty
// Per-batch results + tickets (reset to 0 by their last user each replay).
__device__ float        g_bsum[NB];
__device__ unsigned int g_bcnt[NB];
__device__ unsigned int g_tick_b[NB];
__device__ unsigned int g_tick_g;

__global__ __launch_bounds__(TH) void bcl_fused(const float* __restrict__ bins,
                                                const float* __restrict__ tdm,
                                                const int*   __restrict__ mask,
                                                float*       __restrict__ out) {
    const int batch = blockIdx.x / BPB;
    const int blk   = blockIdx.x % BPB;
    const int bid   = blockIdx.x;
    const int tid   = threadIdx.x;

    __shared__ float sb[NSEG];          // sorted bins + inf pad (for distances)
    __shared__ float ez[256];           // Eytzinger tree, nodes 1..255
    __shared__ int   spmax[NSEG];
    __shared__ int   spmin[NSEG];
    __shared__ int   sflag;             // any invalid pixel seen
    __shared__ float        wl[TH / 32];
    __shared__ unsigned int wc[TH / 32];
    __shared__ unsigned int s_tick;

    if (tid < DB)   sb[tid] = bins[batch * DB + tid];
    if (tid == DB)  sb[DB]  = __int_as_float(INF_BITS);
    for (int i = tid; i < NSEG; i += TH) { spmax[i] = -1; spmin[i] = INF_BITS; }
    if (tid == 0) { sflag = 0; ez[0] = 0.0f; }
    __syncthreads();

    // Build BFS tree: node i (1..255) at depth d holds sorted rank
    // r = p*2^(8-d) + 2^(7-d) - 1 (p = position in level); ranks >= 128 pad +inf.
    if (tid >= 1) {
        const int d = 31 - __clz(tid);
        const int p = tid - (1 << d);
        const int r = p * (1 << (8 - d)) + (1 << (7 - d)) - 1;
        ez[tid] = (r < DB) ? sb[r] : __int_as_float(INF_BITS);
    }
    __syncthreads();

    const float b0 = sb[0];
    float loss1 = 0.0f;
    unsigned int cnt = 0;
    bool sawInvalid = false;

    const int base = batch * HW + blk * PPB;
    const float4* t4 = (const float4*)(tdm + base);
    const int4*   m4 = (const int4*)(mask + base);

    #pragma unroll
    for (int it = 0; it < PPB / (4 * TH); it++) {       // 2 iterations, 8 px/thread
        const int i = it * TH + tid;
        const float4 tv = t4[i];
        const int4   mv = m4[i];
        const float gv[4] = {tv.x, tv.y, tv.z, tv.w};
        const int   mk[4] = {mv.x, mv.y, mv.z, mv.w};
        #pragma unroll
        for (int k = 0; k < 4; k++) {
            const bool valid = (mk[k] != 0);
            const float g = valid ? fmaxf(gv[k], b0) : b0;
            // Eytzinger descent: after 8 steps, s = i - 256 = #bins <= g in [1,128].
            int n = 1;
            #pragma unroll
            for (int bs = 0; bs < 8; bs++) n = 2 * n + (ez[n] <= g);
            const int s = n - 256;
            loss1 += fminf(g - sb[s - 1], sb[s] - g);    // 0 for invalid (g==b0)
            if (valid) {
                cnt++;
                const int gi = __float_as_int(g);        // g>0: int order == float order
                if (gi > spmax[s]) atomicMax(&spmax[s], gi);   // monotonic: race-safe
                if (gi < spmin[s]) atomicMin(&spmin[s], gi);
            } else {
                sawInvalid = true;
            }
        }
    }
    if (sawInvalid) sflag = 1;                           // benign race
    __syncthreads();

    if (tid == 0 && sflag) {                             // one b0 update for all invalids
        int n = 1;
        for (int bs = 0; bs < 8; bs++) n = 2 * n + (ez[n] <= b0);
        const int s = n - 256;
        const int bi = __float_as_int(b0);
        if (bi > spmax[s]) atomicMax(&spmax[s], bi);
        if (bi < spmin[s]) atomicMin(&spmin[s], bi);
    }

    // block reduce loss1 & count
    #pragma unroll
    for (int off = 16; off; off >>= 1) {
        loss1 += __shfl_down_sync(0xFFFFFFFFu, loss1, off);
        cnt   += __shfl_down_sync(0xFFFFFFFFu, cnt,   off);
    }
    if ((tid & 31) == 0) { wl[tid >> 5] = loss1; wc[tid >> 5] = cnt; }
    __syncthreads();

    // publish partials
    if (tid == 0) {
        float L = 0.0f; unsigned int C = 0;
        #pragma unroll
        for (int w = 0; w < TH / 32; w++) { L += wl[w]; C += wc[w]; }
        g_pl1[bid] = L; g_pcnt[bid] = C;
    }
    for (int i = tid; i < NSEG; i += TH) {
        g_pmax[bid * NSEG + i] = spmax[i];
        g_pmin[bid * NSEG + i] = spmin[i];
    }
    __threadfence();
    if (tid == 0) s_tick = atomicAdd(&g_tick_b[batch], 1u);
    __syncthreads();
    if (s_tick != BPB - 1) return;

    // ---------------- batch finalizer (one block per batch) ----------------
    __threadfence();
    if (tid == 0) g_tick_b[batch] = 0;                   // reset for next replay

    __shared__ float pref[NSEG], suf[NSEG];
    if (tid < NSEG) {
        int mx = -1, mn = INF_BITS;
        const int mbase = (batch * BPB) * NSEG + tid;
        #pragma unroll 4
        for (int b = 0; b < BPB; b++) {
            mx = max(mx, g_pmax[mbase + b * NSEG]);
            mn = min(mn, g_pmin[mbase + b * NSEG]);
        }
        pref[tid] = (mx == -1)       ? -1e30f : __int_as_float(mx);
        suf [tid] = (mn == INF_BITS) ?  1e30f : __int_as_float(mn);
    }
    float L = 0.0f; unsigned int C = 0;
    if (tid < 32) {
        if (tid < BPB) { L = g_pl1[batch * BPB + tid]; C = g_pcnt[batch * BPB + tid]; }
        #pragma unroll
        for (int off = 16; off; off >>= 1) {
            L += __shfl_down_sync(0xFFFFFFFFu, L, off);
            C += __shfl_down_sync(0xFFFFFFFFu, C, off);
        }
    }
    __syncthreads();

    if (tid == 0) {                                      // in-place 129-entry scans
        float r = -1e30f;
        for (int s = 0; s < NSEG; s++) { r = fmaxf(r, pref[s]); pref[s] = r; }
        float r2 = 1e30f;
        for (int s = NSEG - 1; s >= 0; s--) { r2 = fminf(r2, suf[s]); suf[s] = r2; }
    }
    __syncthreads();

    float v = 0.0f;
    if (tid < DB) {
        const float bj = sb[tid];
        v = fminf(bj - pref[tid], suf[tid + 1] - bj);    // exact per-bin min dist
    }
    #pragma unroll
    for (int off = 16; off; off >>= 1) v += __shfl_down_sync(0xFFFFFFFFu, v, off);
    if ((tid & 31) == 0) wl[tid >> 5] = v;
    __syncthreads();

    if (tid == 0) {
        const float loss2 = wl[0] + wl[1] + wl[2] + wl[3];
        g_bsum[batch] = L + loss2;
        g_bcnt[batch] = C;
        __threadfence();
        const unsigned int t2 = atomicAdd(&g_tick_g, 1u);
        if (t2 == NB - 1) {                              // global finalizer
            g_tick_g = 0;
            __threadfence();
            unsigned int tot = 0;
            #pragma unroll
            for (int b = 0; b < NB; b++) tot += g_bcnt[b];
            const float inv = 1.0f / (float)tot;
            #pragma unroll
            for (int b = 0; b < NB; b++) out[b] = g_bsum[b] * inv;
        }
    }
}

extern "C" void kernel_launch(void* const* d_in, const int* in_sizes, int n_in,
                              void* d_out, int out_size) {
    const float* bins = (const float*)d_in[0];
    const float* tdm  = (const float*)d_in[1];
    const int*   msk  = (const int*)d_in[2];
    float*       out  = (float*)d_out;

    bcl_fused<<<NB * BPB, TH>>>(bins, tdm, msk, out);
}